// round 7
// baseline (speedup 1.0000x reference)
#include <cuda_runtime.h>
#include <cuda_bf16.h>

// Problem constants
#define BB 16
#define LL 512
#define HS 1024
#define HH 16
#define DD 64
#define MROWS (BB*LL)        // 8192

// -------------------- scratch (allocation-free) --------------------
__device__ float g_vh[BB*HH*LL*DD];   // [B,H,L,D]
__device__ float g_kh[BB*HH*LL*DD];
__device__ float g_qh[BB*HH*LL*DD];
__device__ float g_qn[BB*HH*LL*DD];   // modulated q
__device__ float g_att[BB*LL*HS];     // [B,L,H*D]

// ------------------ bf16 helpers ------------------
__device__ __forceinline__ unsigned pack2bf(__nv_bfloat16 a, __nv_bfloat16 b) {
    __nv_bfloat162 t; t.x = a; t.y = b;
    return reinterpret_cast<unsigned&>(t);
}

// split two floats into packed bf16 hi pair + bf16 lo pair (k-adjacent: x0 low half)
__device__ __forceinline__ void bsplit2(float x0, float x1, unsigned &hi, unsigned &lo) {
    __nv_bfloat16 h0 = __float2bfloat16(x0);
    __nv_bfloat16 h1 = __float2bfloat16(x1);
    __nv_bfloat16 l0 = __float2bfloat16(x0 - __bfloat162float(h0));
    __nv_bfloat16 l1 = __float2bfloat16(x1 - __bfloat162float(h1));
    hi = pack2bf(h0, h1);
    lo = pack2bf(l0, l1);
}

__device__ __forceinline__ void mma_bf16(float d[4],
                                         unsigned a0, unsigned a1, unsigned a2, unsigned a3,
                                         unsigned b0, unsigned b1)
{
    asm volatile(
        "mma.sync.aligned.m16n8k16.row.col.f32.bf16.bf16.f32 "
        "{%0,%1,%2,%3}, {%4,%5,%6,%7}, {%8,%9}, {%0,%1,%2,%3};\n"
        : "+f"(d[0]), "+f"(d[1]), "+f"(d[2]), "+f"(d[3])
        : "r"(a0), "r"(a1), "r"(a2), "r"(a3), "r"(b0), "r"(b1));
}

// ====================================================================
// bf16 tensor-core GEMM with 3-term compensation, 2-stage smem pipeline
// (unchanged from R6 — running at the legacy-HMMA issue roofline).
// ====================================================================
#define BP 40                  // bf16 pitch
#define GST (4*128*BP)         // bf16 elems per stage (AsHi,AsLo,BsHi,BsLo)

template<int OUTMODE>
__global__ void __launch_bounds__(256, 1) gemm_bf16(const float* __restrict__ A,
                                                    const float* __restrict__ Bw,
                                                    float* __restrict__ C,
                                                    int M, int N, int K)
{
    extern __shared__ float smf[];
    __nv_bfloat16* smb = (__nv_bfloat16*)smf;

    const int tid  = threadIdx.x;
    const int br   = blockIdx.y;
    const int bc   = blockIdx.x;
    const int wid  = tid >> 5;
    const int lane = tid & 31;
    const int g    = lane >> 2;
    const int tig  = lane & 3;

    const int wm = wid >> 2;
    const int wn = wid & 3;

    const float* Ab = A  + (long)br * 128 * K;
    const float* Bb = Bw + (long)bc * 128 * K;

    float acc[4][4][4];
#pragma unroll
    for (int mt = 0; mt < 4; ++mt)
#pragma unroll
        for (int nt = 0; nt < 4; ++nt)
#pragma unroll
            for (int r = 0; r < 4; ++r) acc[mt][nt][r] = 0.f;

    const int ldrow = tid >> 3;          // 0..31 (advance by 32)
    const int ldkq  = tid & 7;           // float4 slot (k = ldkq*4..+3)

    auto store_tile = [&](int s, const float4* av, const float4* bv) {
        __nv_bfloat16* AsHi = smb + s * GST;
        __nv_bfloat16* AsLo = AsHi + 128 * BP;
        __nv_bfloat16* BsHi = AsLo + 128 * BP;
        __nv_bfloat16* BsLo = BsHi + 128 * BP;
#pragma unroll
        for (int it = 0; it < 4; ++it) {
            int row = ldrow + it * 32;
            float4 a = av[it];
            unsigned h01, l01, h23, l23;
            bsplit2(a.x, a.y, h01, l01);
            bsplit2(a.z, a.w, h23, l23);
            *(uint2*)(AsHi + row * BP + ldkq * 4) = make_uint2(h01, h23);
            *(uint2*)(AsLo + row * BP + ldkq * 4) = make_uint2(l01, l23);
            float4 b = bv[it];
            bsplit2(b.x, b.y, h01, l01);
            bsplit2(b.z, b.w, h23, l23);
            *(uint2*)(BsHi + row * BP + ldkq * 4) = make_uint2(h01, h23);
            *(uint2*)(BsLo + row * BP + ldkq * 4) = make_uint2(l01, l23);
        }
    };

    float4 pfA[4], pfB[4];
#pragma unroll
    for (int it = 0; it < 4; ++it) {
        int row = ldrow + it * 32;
        pfA[it] = *(const float4*)(Ab + (long)row * K + ldkq * 4);
        pfB[it] = *(const float4*)(Bb + (long)row * K + ldkq * 4);
    }
    store_tile(0, pfA, pfB);
    __syncthreads();

    const int nKt = K / 32;
    for (int kt = 0; kt < nKt; ++kt) {
        const int s = kt & 1;
        if (kt + 1 < nKt) {
            int k0 = (kt + 1) * 32;
#pragma unroll
            for (int it = 0; it < 4; ++it) {
                int row = ldrow + it * 32;
                pfA[it] = *(const float4*)(Ab + (long)row * K + k0 + ldkq * 4);
                pfB[it] = *(const float4*)(Bb + (long)row * K + k0 + ldkq * 4);
            }
        }

        const __nv_bfloat16* AsHi = smb + s * GST;
        const __nv_bfloat16* AsLo = AsHi + 128 * BP;
        const __nv_bfloat16* BsHi = AsLo + 128 * BP;
        const __nv_bfloat16* BsLo = BsHi + 128 * BP;

        // 2 k-steps of 16
#pragma unroll
        for (int ks = 0; ks < 2; ++ks) {
            const int kk = ks * 16;
            unsigned ah[4][4], al[4][4];
#pragma unroll
            for (int mt = 0; mt < 4; ++mt) {
                int m = wm * 64 + mt * 16 + g;
                const __nv_bfloat16* pH = AsHi + m * BP + kk + tig * 2;
                const __nv_bfloat16* pL = AsLo + m * BP + kk + tig * 2;
                ah[mt][0] = *(const unsigned*)(pH);
                ah[mt][1] = *(const unsigned*)(pH + 8 * BP);
                ah[mt][2] = *(const unsigned*)(pH + 8);
                ah[mt][3] = *(const unsigned*)(pH + 8 * BP + 8);
                al[mt][0] = *(const unsigned*)(pL);
                al[mt][1] = *(const unsigned*)(pL + 8 * BP);
                al[mt][2] = *(const unsigned*)(pL + 8);
                al[mt][3] = *(const unsigned*)(pL + 8 * BP + 8);
            }
            unsigned bh[4][2], bl[4][2];
#pragma unroll
            for (int nt = 0; nt < 4; ++nt) {
                int n = wn * 32 + nt * 8 + g;
                const __nv_bfloat16* pH = BsHi + n * BP + kk + tig * 2;
                const __nv_bfloat16* pL = BsLo + n * BP + kk + tig * 2;
                bh[nt][0] = *(const unsigned*)(pH);
                bh[nt][1] = *(const unsigned*)(pH + 8);
                bl[nt][0] = *(const unsigned*)(pL);
                bl[nt][1] = *(const unsigned*)(pL + 8);
            }
#pragma unroll
            for (int mt = 0; mt < 4; ++mt) {
#pragma unroll
                for (int nt = 0; nt < 4; ++nt) {
                    mma_bf16(acc[mt][nt], ah[mt][0], ah[mt][1], ah[mt][2], ah[mt][3],
                             bh[nt][0], bh[nt][1]);
                    mma_bf16(acc[mt][nt], al[mt][0], al[mt][1], al[mt][2], al[mt][3],
                             bh[nt][0], bh[nt][1]);
                    mma_bf16(acc[mt][nt], ah[mt][0], ah[mt][1], ah[mt][2], ah[mt][3],
                             bl[nt][0], bl[nt][1]);
                }
            }
        }
        if (kt + 1 < nKt) {
            store_tile(s ^ 1, pfA, pfB);
        }
        __syncthreads();
    }

#pragma unroll
    for (int mt = 0; mt < 4; ++mt) {
#pragma unroll
        for (int nt = 0; nt < 4; ++nt) {
            int jj = bc * 128 + wn * 32 + nt * 8 + tig * 2;
#pragma unroll
            for (int half = 0; half < 2; ++half) {
                int ii = br * 128 + wm * 64 + mt * 16 + g + half * 8;
                float2 val;
                val.x = acc[mt][nt][half * 2 + 0];
                val.y = acc[mt][nt][half * 2 + 1];
                if (OUTMODE == 0) {
                    *(float2*)(C + (long)ii * N + jj) = val;
                } else {
                    int b = ii >> 9, l = ii & 511;
                    int h = jj >> 6, d = jj & 63;
                    *(float2*)(C + (((long)(b * 16 + h) * 512) + l) * 64 + d) = val;
                }
            }
        }
    }
}

// ====================================================================
// Tensor-core flash attention, all-bf16 3-term.
// R7: BM=64 q rows, 128 threads (4 warps, one m16 strip each),
// __launch_bounds__(128, 2) -> 2 independent CTAs per SM so one CTA's
// mma issues while the other sits in softmax / load latency.
// ====================================================================
#define KP  72   // bf16 pitch for K tiles
#define VTP 36   // unsigned pitch for transposed V (packed j-pairs)
#define PP  36   // unsigned pitch for P (packed j-pairs)
#define QSP 68   // fp32 pitch for Q staging
// smem float offsets (BM=64)
#define OFF_KHI 0                         // bf16 KHi: 64*72 bf16 = 2304 floats
#define OFF_KLO 2304
#define OFF_VTH 4608                      // unsigned VtHi: 64*36 = 2304
#define OFF_VTL 6912
#define OFF_PQ  9216                      // Q stage (64*68=4352f) aliased with PH+PL (2*2304)
#define OFF_MS  13824                     // mask bytes: 64*64 = 1024 floats
#define ATTN_SMEM_FLOATS 14848            // 59392 B

__global__ void __launch_bounds__(128, 2) attn_tc(
    const float* __restrict__ Q,
    const float* __restrict__ Kb, long kBS, long kHS, int kRS,
    const float* __restrict__ Vb, long vBS, long vHS, int vRS,
    const unsigned int* __restrict__ mask,
    float* __restrict__ Ob, long oBS, long oHS, int oRS,
    int residual)
{
    extern __shared__ float sm[];
    __nv_bfloat16* Khi = (__nv_bfloat16*)(sm + OFF_KHI);
    __nv_bfloat16* Klo = (__nv_bfloat16*)(sm + OFF_KLO);
    unsigned* VtHi = (unsigned*)(sm + OFF_VTH);
    unsigned* VtLo = (unsigned*)(sm + OFF_VTL);
    float*    Qs   = sm + OFF_PQ;                 // staging only (pre-loop)
    unsigned* PH   = (unsigned*)(sm + OFF_PQ);    // aliases Qs after frag extract
    unsigned* PL   = PH + 64 * PP;
    unsigned char* Ms = (unsigned char*)(sm + OFF_MS);

    const int b  = blockIdx.z;
    const int h  = blockIdx.y;
    const int q0 = blockIdx.x * 64;

    const float* Qp = Q + (((long)(b*16 + h) * 512) + q0) * 64;
    const float* Kp = Kb + (long)b * kBS + (long)h * kHS;
    const float* Vp = Vb + (long)b * vBS + (long)h * vHS;
    const unsigned int* Mp = mask + (long)b * LL * LL + (long)q0 * LL;
    float* Op = Ob + (long)b * oBS + (long)h * oHS + (long)q0 * oRS;

    const int tid  = threadIdx.x;
    const int w    = tid >> 5;     // 0..3
    const int lane = tid & 31;
    const int g    = lane >> 2;    // 0..7
    const int tig  = lane & 3;     // 0..3
    const int r0   = w * 16 + g;   // block-local q row (also r0+8), 0..63

    // ---- stage Q, extract bf16 hi/lo fragments into registers ----
#pragma unroll
    for (int it = 0; it < 8; ++it) {
        int f = tid + it * 128;          // 0..1023 float4
        int row = f >> 4, c4 = f & 15;
        float4 v = *(const float4*)(Qp + (long)row * 64 + c4 * 4);
        float* dst = Qs + row * QSP + c4 * 4;
        dst[0] = v.x; dst[1] = v.y; dst[2] = v.z; dst[3] = v.w;
    }
    __syncthreads();

    unsigned qh[4][4], ql[4][4];   // 4 k16-chunks, 4 packed regs each
#pragma unroll
    for (int kc = 0; kc < 4; ++kc) {
        const float* p0 = Qs + (r0)     * QSP + kc * 16 + tig * 2;
        const float* p1 = Qs + (r0 + 8) * QSP + kc * 16 + tig * 2;
        bsplit2(p0[0], p0[1], qh[kc][0], ql[kc][0]);
        bsplit2(p1[0], p1[1], qh[kc][1], ql[kc][1]);
        bsplit2(p0[8], p0[9], qh[kc][2], ql[kc][2]);
        bsplit2(p1[8], p1[9], qh[kc][3], ql[kc][3]);
    }
    // NOTE: Qs memory is reused as PH/PL inside the loop. All warps have read
    // their Q fragments before the first PH write (separated by the
    // __syncthreads after the first K/V/mask load below).

    float oacc[8][4];
#pragma unroll
    for (int nt = 0; nt < 8; ++nt)
#pragma unroll
        for (int i = 0; i < 4; ++i) oacc[nt][i] = 0.f;

    float m0 = -1e30f, m1 = -1e30f, l0 = 0.f, l1 = 0.f;

    for (int kt = 0; kt < 8; ++kt) {
        const int k0 = kt * 64;

        // ---- load K (bf16 hi/lo, row-major) ----
#pragma unroll
        for (int it = 0; it < 8; ++it) {
            int f = tid + it * 128;      // 0..1023
            int row = f >> 4, c4 = f & 15;
            float4 kv = *(const float4*)(Kp + (long)(k0 + row) * kRS + c4 * 4);
            unsigned h01, l01, h23, l23;
            bsplit2(kv.x, kv.y, h01, l01);
            bsplit2(kv.z, kv.w, h23, l23);
            *(uint2*)(Khi + row * KP + c4 * 4) = make_uint2(h01, h23);
            *(uint2*)(Klo + row * KP + c4 * 4) = make_uint2(l01, l23);
        }
        // ---- load V transposed: Vt[d][jp] = pack(V[2jp][d], V[2jp+1][d]) ----
#pragma unroll
        for (int it = 0; it < 4; ++it) {
            int idx = tid + it * 128;    // 0..511
            int jp = idx & 31;           // j-pair index
            int c4 = idx >> 5;           // 0..15 -> d base c4*4
            const float* v0 = Vp + (long)(k0 + 2 * jp) * vRS + c4 * 4;
            float4 a = *(const float4*)v0;
            float4 bq = *(const float4*)(v0 + vRS);
            unsigned hh, ll;
            bsplit2(a.x, bq.x, hh, ll);
            VtHi[(c4 * 4 + 0) * VTP + jp] = hh; VtLo[(c4 * 4 + 0) * VTP + jp] = ll;
            bsplit2(a.y, bq.y, hh, ll);
            VtHi[(c4 * 4 + 1) * VTP + jp] = hh; VtLo[(c4 * 4 + 1) * VTP + jp] = ll;
            bsplit2(a.z, bq.z, hh, ll);
            VtHi[(c4 * 4 + 2) * VTP + jp] = hh; VtLo[(c4 * 4 + 2) * VTP + jp] = ll;
            bsplit2(a.w, bq.w, hh, ll);
            VtHi[(c4 * 4 + 3) * VTP + jp] = hh; VtLo[(c4 * 4 + 3) * VTP + jp] = ll;
        }
        // ---- mask tile (64x64) ----
#pragma unroll
        for (int it = 0; it < 8; ++it) {
            int u = tid + it * 128;      // 0..1023
            int row = u >> 4, c4 = u & 15;
            uint4 m4 = *(const uint4*)(Mp + (long)row * LL + k0 + c4 * 4);
            uchar4 pk;
            pk.x = m4.x ? 1 : 0;
            pk.y = m4.y ? 1 : 0;
            pk.z = m4.z ? 1 : 0;
            pk.w = m4.w ? 1 : 0;
            ((uchar4*)Ms)[row * 16 + c4] = pk;
        }
        __syncthreads();

        // ---- S = Q K^T (3-term bf16, k16) ----
        float sacc[8][4];
#pragma unroll
        for (int nt = 0; nt < 8; ++nt) {
#pragma unroll
            for (int i = 0; i < 4; ++i) sacc[nt][i] = 0.f;
#pragma unroll
            for (int kc = 0; kc < 4; ++kc) {
                const __nv_bfloat16* pH = Khi + (nt * 8 + g) * KP + kc * 16 + tig * 2;
                const __nv_bfloat16* pL = Klo + (nt * 8 + g) * KP + kc * 16 + tig * 2;
                unsigned bh0 = *(const unsigned*)(pH);
                unsigned bh1 = *(const unsigned*)(pH + 8);
                unsigned bl0 = *(const unsigned*)(pL);
                unsigned bl1 = *(const unsigned*)(pL + 8);
                mma_bf16(sacc[nt], qh[kc][0], qh[kc][1], qh[kc][2], qh[kc][3], bh0, bh1);
                mma_bf16(sacc[nt], ql[kc][0], ql[kc][1], ql[kc][2], ql[kc][3], bh0, bh1);
                mma_bf16(sacc[nt], qh[kc][0], qh[kc][1], qh[kc][2], qh[kc][3], bl0, bl1);
            }
        }

        // ---- scale + mask ----
#pragma unroll
        for (int nt = 0; nt < 8; ++nt) {
            uchar2 mA = *(const uchar2*)(Ms + (r0)     * 64 + nt * 8 + tig * 2);
            uchar2 mB = *(const uchar2*)(Ms + (r0 + 8) * 64 + nt * 8 + tig * 2);
            sacc[nt][0] = mA.x ? -1e9f : sacc[nt][0] * 0.125f;
            sacc[nt][1] = mA.y ? -1e9f : sacc[nt][1] * 0.125f;
            sacc[nt][2] = mB.x ? -1e9f : sacc[nt][2] * 0.125f;
            sacc[nt][3] = mB.y ? -1e9f : sacc[nt][3] * 0.125f;
        }

        // ---- online softmax (warp-local, quad reductions) ----
        float mx0 = -3.0e38f, mx1 = -3.0e38f;
#pragma unroll
        for (int nt = 0; nt < 8; ++nt) {
            mx0 = fmaxf(mx0, fmaxf(sacc[nt][0], sacc[nt][1]));
            mx1 = fmaxf(mx1, fmaxf(sacc[nt][2], sacc[nt][3]));
        }
        mx0 = fmaxf(mx0, __shfl_xor_sync(0xffffffffu, mx0, 1));
        mx0 = fmaxf(mx0, __shfl_xor_sync(0xffffffffu, mx0, 2));
        mx1 = fmaxf(mx1, __shfl_xor_sync(0xffffffffu, mx1, 1));
        mx1 = fmaxf(mx1, __shfl_xor_sync(0xffffffffu, mx1, 2));

        float mn0 = fmaxf(m0, mx0), mn1 = fmaxf(m1, mx1);
        float al0 = __expf(m0 - mn0), al1 = __expf(m1 - mn1);
        m0 = mn0; m1 = mn1;

        float sum0 = 0.f, sum1 = 0.f;
#pragma unroll
        for (int nt = 0; nt < 8; ++nt) {
            float p00 = __expf(sacc[nt][0] - m0);
            float p01 = __expf(sacc[nt][1] - m0);
            float p10 = __expf(sacc[nt][2] - m1);
            float p11 = __expf(sacc[nt][3] - m1);
            sum0 += p00 + p01;
            sum1 += p10 + p11;
            unsigned hh, ll;
            bsplit2(p00, p01, hh, ll);
            PH[(r0)     * PP + nt * 4 + tig] = hh;
            PL[(r0)     * PP + nt * 4 + tig] = ll;
            bsplit2(p10, p11, hh, ll);
            PH[(r0 + 8) * PP + nt * 4 + tig] = hh;
            PL[(r0 + 8) * PP + nt * 4 + tig] = ll;
        }
        sum0 += __shfl_xor_sync(0xffffffffu, sum0, 1);
        sum0 += __shfl_xor_sync(0xffffffffu, sum0, 2);
        sum1 += __shfl_xor_sync(0xffffffffu, sum1, 1);
        sum1 += __shfl_xor_sync(0xffffffffu, sum1, 2);
        l0 = l0 * al0 + sum0;
        l1 = l1 * al1 + sum1;

#pragma unroll
        for (int nt = 0; nt < 8; ++nt) {
            oacc[nt][0] *= al0; oacc[nt][1] *= al0;
            oacc[nt][2] *= al1; oacc[nt][3] *= al1;
        }
        __syncwarp();

        // ---- O += P V (3-term bf16, k16) ----
#pragma unroll
        for (int kc = 0; kc < 4; ++kc) {
            const unsigned* pHr0 = PH + (r0)     * PP + kc * 8 + tig;
            const unsigned* pHr8 = PH + (r0 + 8) * PP + kc * 8 + tig;
            const unsigned* pLr0 = PL + (r0)     * PP + kc * 8 + tig;
            const unsigned* pLr8 = PL + (r0 + 8) * PP + kc * 8 + tig;
            unsigned ph0 = pHr0[0], ph1 = pHr8[0], ph2 = pHr0[4], ph3 = pHr8[4];
            unsigned pl0 = pLr0[0], pl1 = pLr8[0], pl2 = pLr0[4], pl3 = pLr8[4];
#pragma unroll
            for (int nt = 0; nt < 8; ++nt) {
                const unsigned* vH = VtHi + (nt * 8 + g) * VTP + kc * 8 + tig;
                const unsigned* vL = VtLo + (nt * 8 + g) * VTP + kc * 8 + tig;
                unsigned bh0 = vH[0], bh1 = vH[4];
                unsigned bl0 = vL[0], bl1 = vL[4];
                mma_bf16(oacc[nt], ph0, ph1, ph2, ph3, bh0, bh1);
                mma_bf16(oacc[nt], pl0, pl1, pl2, pl3, bh0, bh1);
                mma_bf16(oacc[nt], ph0, ph1, ph2, ph3, bl0, bl1);
            }
        }
        __syncthreads();
    }

    // ---- finalize: /l, residual (from global Q), store ----
    float inv0 = 1.0f / l0, inv1 = 1.0f / l1;
#pragma unroll
    for (int nt = 0; nt < 8; ++nt) {
        int c = nt * 8 + tig * 2;
        float2 v0 = make_float2(oacc[nt][0] * inv0, oacc[nt][1] * inv0);
        float2 v1 = make_float2(oacc[nt][2] * inv1, oacc[nt][3] * inv1);
        if (residual) {
            float2 qres0 = *(const float2*)(Qp + (long)(r0)     * 64 + c);
            float2 qres1 = *(const float2*)(Qp + (long)(r0 + 8) * 64 + c);
            v0.x += qres0.x; v0.y += qres0.y;
            v1.x += qres1.x; v1.y += qres1.y;
        }
        *(float2*)(Op + (long)(r0)     * oRS + c) = v0;
        *(float2*)(Op + (long)(r0 + 8) * oRS + c) = v1;
    }
}

// ====================================================================
extern "C" void kernel_launch(void* const* d_in, const int* in_sizes, int n_in,
                              void* d_out, int out_size)
{
    (void)in_sizes; (void)n_in; (void)out_size;
    const float* v   = (const float*)d_in[0];
    const float* k   = (const float*)d_in[1];
    const float* q   = (const float*)d_in[2];
    const float* img = (const float*)d_in[3];
    const float* Wv  = (const float*)d_in[4];
    const float* Wk  = (const float*)d_in[5];
    const float* Wq  = (const float*)d_in[6];
    const float* Wm  = (const float*)d_in[7];
    const unsigned int* absm = (const unsigned int*)d_in[8];
    const unsigned int* mask = (const unsigned int*)d_in[9];
    float* out = (float*)d_out;

    float *vh, *kh, *qh, *qn, *att;
    cudaGetSymbolAddress((void**)&vh,  g_vh);
    cudaGetSymbolAddress((void**)&kh,  g_kh);
    cudaGetSymbolAddress((void**)&qh,  g_qh);
    cudaGetSymbolAddress((void**)&qn,  g_qn);
    cudaGetSymbolAddress((void**)&att, g_att);

    const int gsmem = 2 * GST * (int)sizeof(__nv_bfloat16);   // 81920
    cudaFuncSetAttribute(gemm_bf16<0>,
                         cudaFuncAttributeMaxDynamicSharedMemorySize, gsmem);
    cudaFuncSetAttribute(gemm_bf16<1>,
                         cudaFuncAttributeMaxDynamicSharedMemorySize, gsmem);

    dim3 gg(HS / 128, MROWS / 128);   // (8, 64)
    gemm_bf16<1><<<gg, 256, gsmem>>>(v, Wv, vh, MROWS, HS, HS);
    gemm_bf16<1><<<gg, 256, gsmem>>>(k, Wk, kh, MROWS, HS, HS);
    gemm_bf16<1><<<gg, 256, gsmem>>>(q, Wq, qh, MROWS, HS, HS);

    const int asmem = ATTN_SMEM_FLOATS * (int)sizeof(float);   // 59392
    cudaFuncSetAttribute(attn_tc,
                         cudaFuncAttributeMaxDynamicSharedMemorySize, asmem);

    dim3 ga(LL / 64, HH, BB);   // (8, 16, 16) = 2048 CTAs
    // Stage 1: modulate — K=V=img_abs (strided heads), residual, out -> g_qn [B,H,L,D]
    attn_tc<<<ga, 128, asmem>>>(
        qh,
        img, (long)LL * HS, 64L, HS,
        img, (long)LL * HS, 64L, HS,
        absm,
        qn,  (long)HH * LL * DD, (long)LL * DD, DD,
        1);
    // Stage 2: main attention — K=kh, V=vh, out -> g_att [B,L,H*D]
    attn_tc<<<ga, 128, asmem>>>(
        qn,
        kh, (long)HH * LL * DD, (long)LL * DD, DD,
        vh, (long)HH * LL * DD, (long)LL * DD, DD,
        mask,
        att, (long)LL * HS, 64L, HS,
        0);

    gemm_bf16<0><<<gg, 256, gsmem>>>(att, Wm, out, MROWS, HS, HS);
}

// round 9
// speedup vs baseline: 1.6321x; 1.6321x over previous
#include <cuda_runtime.h>
#include <cuda_bf16.h>

// Problem constants
#define BB 16
#define LL 512
#define HS 1024
#define HH 16
#define DD 64
#define MROWS (BB*LL)        // 8192

// -------------------- scratch (allocation-free) --------------------
__device__ float g_vh[BB*HH*LL*DD];   // [B,H,L,D]
__device__ float g_kh[BB*HH*LL*DD];
__device__ float g_qh[BB*HH*LL*DD];
__device__ float g_qn[BB*HH*LL*DD];   // modulated q
__device__ float g_att[BB*LL*HS];     // [B,L,H*D]
__device__ unsigned char g_absm8[BB*LL*LL];   // packed masks (1 byte/elem)
__device__ unsigned char g_mask8[BB*LL*LL];

// ------------------ bf16 helpers ------------------
__device__ __forceinline__ unsigned pack2bf(__nv_bfloat16 a, __nv_bfloat16 b) {
    __nv_bfloat162 t; t.x = a; t.y = b;
    return reinterpret_cast<unsigned&>(t);
}

// split two floats into packed bf16 hi pair + bf16 lo pair (k-adjacent: x0 low half)
__device__ __forceinline__ void bsplit2(float x0, float x1, unsigned &hi, unsigned &lo) {
    __nv_bfloat16 h0 = __float2bfloat16(x0);
    __nv_bfloat16 h1 = __float2bfloat16(x1);
    __nv_bfloat16 l0 = __float2bfloat16(x0 - __bfloat162float(h0));
    __nv_bfloat16 l1 = __float2bfloat16(x1 - __bfloat162float(h1));
    hi = pack2bf(h0, h1);
    lo = pack2bf(l0, l1);
}

__device__ __forceinline__ void mma_bf16(float d[4],
                                         unsigned a0, unsigned a1, unsigned a2, unsigned a3,
                                         unsigned b0, unsigned b1)
{
    asm volatile(
        "mma.sync.aligned.m16n8k16.row.col.f32.bf16.bf16.f32 "
        "{%0,%1,%2,%3}, {%4,%5,%6,%7}, {%8,%9}, {%0,%1,%2,%3};\n"
        : "+f"(d[0]), "+f"(d[1]), "+f"(d[2]), "+f"(d[3])
        : "r"(a0), "r"(a1), "r"(a2), "r"(a3), "r"(b0), "r"(b1));
}

// ====================================================================
// Mask pre-pack: 4-byte mask elements -> 1 byte (nonzero => 1)
// ====================================================================
__global__ void __launch_bounds__(256) pack_masks(const uint4* __restrict__ a,
                                                  const uint4* __restrict__ b,
                                                  uchar4* __restrict__ oa,
                                                  uchar4* __restrict__ ob)
{
    int i = blockIdx.x * blockDim.x + threadIdx.x;   // 0 .. 1048575
    uint4 x = a[i];
    oa[i] = make_uchar4(x.x ? 1 : 0, x.y ? 1 : 0, x.z ? 1 : 0, x.w ? 1 : 0);
    uint4 y = b[i];
    ob[i] = make_uchar4(y.x ? 1 : 0, y.y ? 1 : 0, y.z ? 1 : 0, y.w ? 1 : 0);
}

// ====================================================================
// bf16 tensor-core GEMM with 3-term compensation, 2-stage smem pipeline.
// GEMM3=1: blockIdx.z selects among 3 (A, W, C) triples (merged QKV launch,
//          head-layout output). GEMM3=0: single GEMM, row-major output.
// ====================================================================
#define BP 40                  // bf16 pitch
#define GST (4*128*BP)         // bf16 elems per stage (AsHi,AsLo,BsHi,BsLo)

template<int GEMM3>
__global__ void __launch_bounds__(256, 1) gemm_bf16(
    const float* __restrict__ A0, const float* __restrict__ A1, const float* __restrict__ A2,
    const float* __restrict__ W0, const float* __restrict__ W1, const float* __restrict__ W2,
    float* __restrict__ C0, float* __restrict__ C1, float* __restrict__ C2,
    int M, int N, int K)
{
    extern __shared__ float smf[];
    __nv_bfloat16* smb = (__nv_bfloat16*)smf;

    const float* A;
    const float* Bw;
    float* C;
    if (GEMM3) {
        int z = blockIdx.z;
        A  = (z == 0) ? A0 : (z == 1) ? A1 : A2;
        Bw = (z == 0) ? W0 : (z == 1) ? W1 : W2;
        C  = (z == 0) ? C0 : (z == 1) ? C1 : C2;
    } else {
        A = A0; Bw = W0; C = C0;
    }

    const int tid  = threadIdx.x;
    const int br   = blockIdx.y;
    const int bc   = blockIdx.x;
    const int wid  = tid >> 5;
    const int lane = tid & 31;
    const int g    = lane >> 2;
    const int tig  = lane & 3;

    const int wm = wid >> 2;
    const int wn = wid & 3;

    const float* Ab = A  + (long)br * 128 * K;
    const float* Bb = Bw + (long)bc * 128 * K;

    float acc[4][4][4];
#pragma unroll
    for (int mt = 0; mt < 4; ++mt)
#pragma unroll
        for (int nt = 0; nt < 4; ++nt)
#pragma unroll
            for (int r = 0; r < 4; ++r) acc[mt][nt][r] = 0.f;

    const int ldrow = tid >> 3;
    const int ldkq  = tid & 7;

    auto store_tile = [&](int s, const float4* av, const float4* bv) {
        __nv_bfloat16* AsHi = smb + s * GST;
        __nv_bfloat16* AsLo = AsHi + 128 * BP;
        __nv_bfloat16* BsHi = AsLo + 128 * BP;
        __nv_bfloat16* BsLo = BsHi + 128 * BP;
#pragma unroll
        for (int it = 0; it < 4; ++it) {
            int row = ldrow + it * 32;
            float4 a = av[it];
            unsigned h01, l01, h23, l23;
            bsplit2(a.x, a.y, h01, l01);
            bsplit2(a.z, a.w, h23, l23);
            *(uint2*)(AsHi + row * BP + ldkq * 4) = make_uint2(h01, h23);
            *(uint2*)(AsLo + row * BP + ldkq * 4) = make_uint2(l01, l23);
            float4 b = bv[it];
            bsplit2(b.x, b.y, h01, l01);
            bsplit2(b.z, b.w, h23, l23);
            *(uint2*)(BsHi + row * BP + ldkq * 4) = make_uint2(h01, h23);
            *(uint2*)(BsLo + row * BP + ldkq * 4) = make_uint2(l01, l23);
        }
    };

    float4 pfA[4], pfB[4];
#pragma unroll
    for (int it = 0; it < 4; ++it) {
        int row = ldrow + it * 32;
        pfA[it] = *(const float4*)(Ab + (long)row * K + ldkq * 4);
        pfB[it] = *(const float4*)(Bb + (long)row * K + ldkq * 4);
    }
    store_tile(0, pfA, pfB);
    __syncthreads();

    const int nKt = K / 32;
    for (int kt = 0; kt < nKt; ++kt) {
        const int s = kt & 1;
        if (kt + 1 < nKt) {
            int k0 = (kt + 1) * 32;
#pragma unroll
            for (int it = 0; it < 4; ++it) {
                int row = ldrow + it * 32;
                pfA[it] = *(const float4*)(Ab + (long)row * K + k0 + ldkq * 4);
                pfB[it] = *(const float4*)(Bb + (long)row * K + k0 + ldkq * 4);
            }
        }

        const __nv_bfloat16* AsHi = smb + s * GST;
        const __nv_bfloat16* AsLo = AsHi + 128 * BP;
        const __nv_bfloat16* BsHi = AsLo + 128 * BP;
        const __nv_bfloat16* BsLo = BsHi + 128 * BP;

#pragma unroll
        for (int ks = 0; ks < 2; ++ks) {
            const int kk = ks * 16;
            unsigned ah[4][4], al[4][4];
#pragma unroll
            for (int mt = 0; mt < 4; ++mt) {
                int m = wm * 64 + mt * 16 + g;
                const __nv_bfloat16* pH = AsHi + m * BP + kk + tig * 2;
                const __nv_bfloat16* pL = AsLo + m * BP + kk + tig * 2;
                ah[mt][0] = *(const unsigned*)(pH);
                ah[mt][1] = *(const unsigned*)(pH + 8 * BP);
                ah[mt][2] = *(const unsigned*)(pH + 8);
                ah[mt][3] = *(const unsigned*)(pH + 8 * BP + 8);
                al[mt][0] = *(const unsigned*)(pL);
                al[mt][1] = *(const unsigned*)(pL + 8 * BP);
                al[mt][2] = *(const unsigned*)(pL + 8);
                al[mt][3] = *(const unsigned*)(pL + 8 * BP + 8);
            }
            unsigned bh[4][2], bl[4][2];
#pragma unroll
            for (int nt = 0; nt < 4; ++nt) {
                int n = wn * 32 + nt * 8 + g;
                const __nv_bfloat16* pH = BsHi + n * BP + kk + tig * 2;
                const __nv_bfloat16* pL = BsLo + n * BP + kk + tig * 2;
                bh[nt][0] = *(const unsigned*)(pH);
                bh[nt][1] = *(const unsigned*)(pH + 8);
                bl[nt][0] = *(const unsigned*)(pL);
                bl[nt][1] = *(const unsigned*)(pL + 8);
            }
#pragma unroll
            for (int mt = 0; mt < 4; ++mt) {
#pragma unroll
                for (int nt = 0; nt < 4; ++nt) {
                    mma_bf16(acc[mt][nt], ah[mt][0], ah[mt][1], ah[mt][2], ah[mt][3],
                             bh[nt][0], bh[nt][1]);
                    mma_bf16(acc[mt][nt], al[mt][0], al[mt][1], al[mt][2], al[mt][3],
                             bh[nt][0], bh[nt][1]);
                    mma_bf16(acc[mt][nt], ah[mt][0], ah[mt][1], ah[mt][2], ah[mt][3],
                             bl[nt][0], bl[nt][1]);
                }
            }
        }
        if (kt + 1 < nKt) {
            store_tile(s ^ 1, pfA, pfB);
        }
        __syncthreads();
    }

#pragma unroll
    for (int mt = 0; mt < 4; ++mt) {
#pragma unroll
        for (int nt = 0; nt < 4; ++nt) {
            int jj = bc * 128 + wn * 32 + nt * 8 + tig * 2;
#pragma unroll
            for (int half = 0; half < 2; ++half) {
                int ii = br * 128 + wm * 64 + mt * 16 + g + half * 8;
                float2 val;
                val.x = acc[mt][nt][half * 2 + 0];
                val.y = acc[mt][nt][half * 2 + 1];
                if (GEMM3 == 0) {
                    *(float2*)(C + (long)ii * N + jj) = val;
                } else {
                    int b = ii >> 9, l = ii & 511;
                    int h = jj >> 6, d = jj & 63;
                    *(float2*)(C + (((long)(b * 16 + h) * 512) + l) * 64 + d) = val;
                }
            }
        }
    }
}

// ====================================================================
// Tensor-core flash attention, all-bf16 3-term (R6 config, best known).
// R9 deltas: masks arrive pre-packed (1 B/elem, 4x less mask traffic, no
// pack ALU), and the 1/8 softmax scale is folded into the Q fragments.
// ====================================================================
#define KP  72   // bf16 pitch for K tiles
#define VTP 36   // unsigned pitch for transposed V (packed j-pairs)
#define PP  36   // unsigned pitch for P (packed j-pairs)
#define QSP 68   // fp32 pitch for Q staging
#define OFF_KHI 0
#define OFF_KLO 2304
#define OFF_VTH 4608
#define OFF_VTL 6912
#define OFF_PQ  9216
#define OFF_MS  18432
#define ATTN_SMEM_FLOATS 20480            // 81920 B

__global__ void __launch_bounds__(256, 1) attn_tc(
    const float* __restrict__ Q,
    const float* __restrict__ Kb, long kBS, long kHS, int kRS,
    const float* __restrict__ Vb, long vBS, long vHS, int vRS,
    const unsigned char* __restrict__ mask8,
    float* __restrict__ Ob, long oBS, long oHS, int oRS,
    int residual)
{
    extern __shared__ float sm[];
    __nv_bfloat16* Khi = (__nv_bfloat16*)(sm + OFF_KHI);
    __nv_bfloat16* Klo = (__nv_bfloat16*)(sm + OFF_KLO);
    unsigned* VtHi = (unsigned*)(sm + OFF_VTH);
    unsigned* VtLo = (unsigned*)(sm + OFF_VTL);
    float*    Qs   = sm + OFF_PQ;
    unsigned* PH   = (unsigned*)(sm + OFF_PQ);
    unsigned* PL   = PH + 128 * PP;
    unsigned char* Ms = (unsigned char*)(sm + OFF_MS);

    const int b  = blockIdx.z;
    const int h  = blockIdx.y;
    const int q0 = blockIdx.x * 128;

    const float* Qp = Q + (((long)(b*16 + h) * 512) + q0) * 64;
    const float* Kp = Kb + (long)b * kBS + (long)h * kHS;
    const float* Vp = Vb + (long)b * vBS + (long)h * vHS;
    const unsigned char* Mp = mask8 + (long)b * LL * LL + (long)q0 * LL;
    float* Op = Ob + (long)b * oBS + (long)h * oHS + (long)q0 * oRS;

    const int tid  = threadIdx.x;
    const int w    = tid >> 5;
    const int lane = tid & 31;
    const int g    = lane >> 2;
    const int tig  = lane & 3;
    const int r0   = w * 16 + g;

#pragma unroll
    for (int it = 0; it < 8; ++it) {
        int f = tid + it * 256;
        int row = f >> 4, c4 = f & 15;
        float4 v = *(const float4*)(Qp + (long)row * 64 + c4 * 4);
        float* dst = Qs + row * QSP + c4 * 4;
        dst[0] = v.x; dst[1] = v.y; dst[2] = v.z; dst[3] = v.w;
    }
    __syncthreads();

    // Q fragments carry the 1/8 softmax scale.
    unsigned qh[4][4], ql[4][4];
#pragma unroll
    for (int kc = 0; kc < 4; ++kc) {
        const float* p0 = Qs + (r0)     * QSP + kc * 16 + tig * 2;
        const float* p1 = Qs + (r0 + 8) * QSP + kc * 16 + tig * 2;
        bsplit2(p0[0] * 0.125f, p0[1] * 0.125f, qh[kc][0], ql[kc][0]);
        bsplit2(p1[0] * 0.125f, p1[1] * 0.125f, qh[kc][1], ql[kc][1]);
        bsplit2(p0[8] * 0.125f, p0[9] * 0.125f, qh[kc][2], ql[kc][2]);
        bsplit2(p1[8] * 0.125f, p1[9] * 0.125f, qh[kc][3], ql[kc][3]);
    }

    float oacc[8][4];
#pragma unroll
    for (int nt = 0; nt < 8; ++nt)
#pragma unroll
        for (int i = 0; i < 4; ++i) oacc[nt][i] = 0.f;

    float m0 = -1e30f, m1 = -1e30f, l0 = 0.f, l1 = 0.f;

    for (int kt = 0; kt < 8; ++kt) {
        const int k0 = kt * 64;

#pragma unroll
        for (int it = 0; it < 4; ++it) {
            int f = tid + it * 256;
            int row = f >> 4, c4 = f & 15;
            float4 kv = *(const float4*)(Kp + (long)(k0 + row) * kRS + c4 * 4);
            unsigned h01, l01, h23, l23;
            bsplit2(kv.x, kv.y, h01, l01);
            bsplit2(kv.z, kv.w, h23, l23);
            *(uint2*)(Khi + row * KP + c4 * 4) = make_uint2(h01, h23);
            *(uint2*)(Klo + row * KP + c4 * 4) = make_uint2(l01, l23);
        }
#pragma unroll
        for (int it = 0; it < 2; ++it) {
            int idx = tid + it * 256;
            int jp = idx & 31;
            int c4 = idx >> 5;
            const float* v0 = Vp + (long)(k0 + 2 * jp) * vRS + c4 * 4;
            float4 a = *(const float4*)v0;
            float4 bq = *(const float4*)(v0 + vRS);
            unsigned hh, ll;
            bsplit2(a.x, bq.x, hh, ll);
            VtHi[(c4 * 4 + 0) * VTP + jp] = hh; VtLo[(c4 * 4 + 0) * VTP + jp] = ll;
            bsplit2(a.y, bq.y, hh, ll);
            VtHi[(c4 * 4 + 1) * VTP + jp] = hh; VtLo[(c4 * 4 + 1) * VTP + jp] = ll;
            bsplit2(a.z, bq.z, hh, ll);
            VtHi[(c4 * 4 + 2) * VTP + jp] = hh; VtLo[(c4 * 4 + 2) * VTP + jp] = ll;
            bsplit2(a.w, bq.w, hh, ll);
            VtHi[(c4 * 4 + 3) * VTP + jp] = hh; VtLo[(c4 * 4 + 3) * VTP + jp] = ll;
        }
        // ---- mask tile: pre-packed bytes, straight copy (8 KB) ----
#pragma unroll
        for (int it = 0; it < 2; ++it) {
            int u = tid + it * 256;      // 0..511
            int row = u >> 2, c16 = u & 3;
            uint4 m = *(const uint4*)(Mp + (long)row * LL + k0 + c16 * 16);
            ((uint4*)Ms)[row * 4 + c16] = m;
        }
        __syncthreads();

        float sacc[8][4];
#pragma unroll
        for (int nt = 0; nt < 8; ++nt) {
#pragma unroll
            for (int i = 0; i < 4; ++i) sacc[nt][i] = 0.f;
#pragma unroll
            for (int kc = 0; kc < 4; ++kc) {
                const __nv_bfloat16* pH = Khi + (nt * 8 + g) * KP + kc * 16 + tig * 2;
                const __nv_bfloat16* pL = Klo + (nt * 8 + g) * KP + kc * 16 + tig * 2;
                unsigned bh0 = *(const unsigned*)(pH);
                unsigned bh1 = *(const unsigned*)(pH + 8);
                unsigned bl0 = *(const unsigned*)(pL);
                unsigned bl1 = *(const unsigned*)(pL + 8);
                mma_bf16(sacc[nt], qh[kc][0], qh[kc][1], qh[kc][2], qh[kc][3], bh0, bh1);
                mma_bf16(sacc[nt], ql[kc][0], ql[kc][1], ql[kc][2], ql[kc][3], bh0, bh1);
                mma_bf16(sacc[nt], qh[kc][0], qh[kc][1], qh[kc][2], qh[kc][3], bl0, bl1);
            }
        }

        // ---- mask (scale already folded into Q) ----
#pragma unroll
        for (int nt = 0; nt < 8; ++nt) {
            uchar2 mA = *(const uchar2*)(Ms + (r0)     * 64 + nt * 8 + tig * 2);
            uchar2 mB = *(const uchar2*)(Ms + (r0 + 8) * 64 + nt * 8 + tig * 2);
            if (mA.x) sacc[nt][0] = -1e9f;
            if (mA.y) sacc[nt][1] = -1e9f;
            if (mB.x) sacc[nt][2] = -1e9f;
            if (mB.y) sacc[nt][3] = -1e9f;
        }

        float mx0 = -3.0e38f, mx1 = -3.0e38f;
#pragma unroll
        for (int nt = 0; nt < 8; ++nt) {
            mx0 = fmaxf(mx0, fmaxf(sacc[nt][0], sacc[nt][1]));
            mx1 = fmaxf(mx1, fmaxf(sacc[nt][2], sacc[nt][3]));
        }
        mx0 = fmaxf(mx0, __shfl_xor_sync(0xffffffffu, mx0, 1));
        mx0 = fmaxf(mx0, __shfl_xor_sync(0xffffffffu, mx0, 2));
        mx1 = fmaxf(mx1, __shfl_xor_sync(0xffffffffu, mx1, 1));
        mx1 = fmaxf(mx1, __shfl_xor_sync(0xffffffffu, mx1, 2));

        float mn0 = fmaxf(m0, mx0), mn1 = fmaxf(m1, mx1);
        float al0 = __expf(m0 - mn0), al1 = __expf(m1 - mn1);
        m0 = mn0; m1 = mn1;

        float sum0 = 0.f, sum1 = 0.f;
#pragma unroll
        for (int nt = 0; nt < 8; ++nt) {
            float p00 = __expf(sacc[nt][0] - m0);
            float p01 = __expf(sacc[nt][1] - m0);
            float p10 = __expf(sacc[nt][2] - m1);
            float p11 = __expf(sacc[nt][3] - m1);
            sum0 += p00 + p01;
            sum1 += p10 + p11;
            unsigned hh, ll;
            bsplit2(p00, p01, hh, ll);
            PH[(r0)     * PP + nt * 4 + tig] = hh;
            PL[(r0)     * PP + nt * 4 + tig] = ll;
            bsplit2(p10, p11, hh, ll);
            PH[(r0 + 8) * PP + nt * 4 + tig] = hh;
            PL[(r0 + 8) * PP + nt * 4 + tig] = ll;
        }
        sum0 += __shfl_xor_sync(0xffffffffu, sum0, 1);
        sum0 += __shfl_xor_sync(0xffffffffu, sum0, 2);
        sum1 += __shfl_xor_sync(0xffffffffu, sum1, 1);
        sum1 += __shfl_xor_sync(0xffffffffu, sum1, 2);
        l0 = l0 * al0 + sum0;
        l1 = l1 * al1 + sum1;

#pragma unroll
        for (int nt = 0; nt < 8; ++nt) {
            oacc[nt][0] *= al0; oacc[nt][1] *= al0;
            oacc[nt][2] *= al1; oacc[nt][3] *= al1;
        }
        __syncwarp();

#pragma unroll
        for (int kc = 0; kc < 4; ++kc) {
            const unsigned* pHr0 = PH + (r0)     * PP + kc * 8 + tig;
            const unsigned* pHr8 = PH + (r0 + 8) * PP + kc * 8 + tig;
            const unsigned* pLr0 = PL + (r0)     * PP + kc * 8 + tig;
            const unsigned* pLr8 = PL + (r0 + 8) * PP + kc * 8 + tig;
            unsigned ph0 = pHr0[0], ph1 = pHr8[0], ph2 = pHr0[4], ph3 = pHr8[4];
            unsigned pl0 = pLr0[0], pl1 = pLr8[0], pl2 = pLr0[4], pl3 = pLr8[4];
#pragma unroll
            for (int nt = 0; nt < 8; ++nt) {
                const unsigned* vH = VtHi + (nt * 8 + g) * VTP + kc * 8 + tig;
                const unsigned* vL = VtLo + (nt * 8 + g) * VTP + kc * 8 + tig;
                unsigned bh0 = vH[0], bh1 = vH[4];
                unsigned bl0 = vL[0], bl1 = vL[4];
                mma_bf16(oacc[nt], ph0, ph1, ph2, ph3, bh0, bh1);
                mma_bf16(oacc[nt], pl0, pl1, pl2, pl3, bh0, bh1);
                mma_bf16(oacc[nt], ph0, ph1, ph2, ph3, bl0, bl1);
            }
        }
        __syncthreads();
    }

    float inv0 = 1.0f / l0, inv1 = 1.0f / l1;
#pragma unroll
    for (int nt = 0; nt < 8; ++nt) {
        int c = nt * 8 + tig * 2;
        float2 v0 = make_float2(oacc[nt][0] * inv0, oacc[nt][1] * inv0);
        float2 v1 = make_float2(oacc[nt][2] * inv1, oacc[nt][3] * inv1);
        if (residual) {
            float2 qres0 = *(const float2*)(Qp + (long)(r0)     * 64 + c);
            float2 qres1 = *(const float2*)(Qp + (long)(r0 + 8) * 64 + c);
            v0.x += qres0.x; v0.y += qres0.y;
            v1.x += qres1.x; v1.y += qres1.y;
        }
        *(float2*)(Op + (long)(r0)     * oRS + c) = v0;
        *(float2*)(Op + (long)(r0 + 8) * oRS + c) = v1;
    }
}

// ====================================================================
extern "C" void kernel_launch(void* const* d_in, const int* in_sizes, int n_in,
                              void* d_out, int out_size)
{
    (void)in_sizes; (void)n_in; (void)out_size;
    const float* v   = (const float*)d_in[0];
    const float* k   = (const float*)d_in[1];
    const float* q   = (const float*)d_in[2];
    const float* img = (const float*)d_in[3];
    const float* Wv  = (const float*)d_in[4];
    const float* Wk  = (const float*)d_in[5];
    const float* Wq  = (const float*)d_in[6];
    const float* Wm  = (const float*)d_in[7];
    const uint4* absm = (const uint4*)d_in[8];
    const uint4* mask = (const uint4*)d_in[9];
    float* out = (float*)d_out;

    float *vh, *kh, *qh, *qn, *att;
    unsigned char *absm8, *mask8;
    cudaGetSymbolAddress((void**)&vh,  g_vh);
    cudaGetSymbolAddress((void**)&kh,  g_kh);
    cudaGetSymbolAddress((void**)&qh,  g_qh);
    cudaGetSymbolAddress((void**)&qn,  g_qn);
    cudaGetSymbolAddress((void**)&att, g_att);
    cudaGetSymbolAddress((void**)&absm8, g_absm8);
    cudaGetSymbolAddress((void**)&mask8, g_mask8);

    // Pack both masks to bytes (4,194,304 elems each / 4 per thread)
    pack_masks<<<4096, 256>>>(absm, mask, (uchar4*)absm8, (uchar4*)mask8);

    const int gsmem = 2 * GST * (int)sizeof(__nv_bfloat16);   // 81920
    cudaFuncSetAttribute(gemm_bf16<0>,
                         cudaFuncAttributeMaxDynamicSharedMemorySize, gsmem);
    cudaFuncSetAttribute(gemm_bf16<1>,
                         cudaFuncAttributeMaxDynamicSharedMemorySize, gsmem);

    // Merged QKV projection: one launch, blockIdx.z selects the GEMM.
    dim3 g3(HS / 128, MROWS / 128, 3);   // (8, 64, 3)
    gemm_bf16<1><<<g3, 256, gsmem>>>(v, k, q, Wv, Wk, Wq, vh, kh, qh,
                                     MROWS, HS, HS);

    const int asmem = ATTN_SMEM_FLOATS * (int)sizeof(float);   // 81920
    cudaFuncSetAttribute(attn_tc,
                         cudaFuncAttributeMaxDynamicSharedMemorySize, asmem);

    dim3 ga(LL / 128, HH, BB);   // (4, 16, 16)
    // Stage 1: modulate — K=V=img_abs (strided heads), residual, out -> g_qn
    attn_tc<<<ga, 256, asmem>>>(
        qh,
        img, (long)LL * HS, 64L, HS,
        img, (long)LL * HS, 64L, HS,
        absm8,
        qn,  (long)HH * LL * DD, (long)LL * DD, DD,
        1);
    // Stage 2: main attention — K=kh, V=vh, out -> g_att [B,L,H*D]
    attn_tc<<<ga, 256, asmem>>>(
        qn,
        kh, (long)HH * LL * DD, (long)LL * DD, DD,
        vh, (long)HH * LL * DD, (long)LL * DD, DD,
        mask8,
        att, (long)LL * HS, 64L, HS,
        0);

    // Output projection (row-major)
    dim3 gg(HS / 128, MROWS / 128);   // (8, 64)
    gemm_bf16<0><<<gg, 256, gsmem>>>(att, nullptr, nullptr,
                                     Wm, nullptr, nullptr,
                                     out, nullptr, nullptr,
                                     MROWS, HS, HS);
}